// round 1
// baseline (speedup 1.0000x reference)
#include <cuda_runtime.h>
#include <cuda_bf16.h>

#define BATCH 64
#define CH 8
#define NSTAGE 4

// ---------------- device scratch (static, no allocations) ----------------
__device__ float g_ctx[BATCH*32];
__device__ float g_wr[NSTAGE*BATCH*CH*CH*9];
__device__ float g_wt[NSTAGE*BATCH*CH*CH*16];
__device__ float g_wm[NSTAGE*BATCH*CH*CH*25];
__device__ float g_wo[BATCH*3*CH];
__device__ float g_br[NSTAGE*BATCH*CH];
__device__ float g_bt[NSTAGE*BATCH*CH];
__device__ float g_bm[NSTAGE*BATCH*CH];
__device__ float g_bo[BATCH*3];
__device__ float g_xA[BATCH*CH*256*256];
__device__ float g_xB[BATCH*CH*256*256];
__device__ float g_pos[BATCH*CH*128*128];
__device__ float g_neg[BATCH*CH*256*256];
__device__ float g_mul[BATCH*CH*256*256];
__device__ float g_lx[BATCH*CH*128*128];
__device__ float g_xu[BATCH*CH*256*256];
__device__ float g_minpos[BATCH*CH];
__device__ float g_minneg[BATCH*CH];
__device__ float g_minmul[BATCH*CH];

__device__ __forceinline__ float dln_f(float v, float mn) {
    float s = (v > 0.0f) ? 1.0f : -1.0f;
    float a = fabsf(v) - mn;
    return s * logf(logf(a + 2.718281828459045f) + 0.01f);
}

template<int TB>
__device__ __forceinline__ void block_min_write(float v, float* gdst) {
    __shared__ float red[TB];
    int tid = threadIdx.x;
    red[tid] = v;
    __syncthreads();
    #pragma unroll
    for (int s = TB / 2; s > 0; s >>= 1) {
        if (tid < s) red[tid] = fminf(red[tid], red[tid + s]);
        __syncthreads();
    }
    if (tid == 0) *gdst = red[0];
}

// ---------------- gather: ctx + initial x ----------------
__global__ void k_gather(const int* __restrict__ ids,
                         const float* __restrict__ cc,
                         const float* __restrict__ lat) {
    int t = blockIdx.x * blockDim.x + threadIdx.x;
    int T = gridDim.x * blockDim.x;
    for (int i = t; i < BATCH * 32; i += T) {
        int b = i >> 5;
        g_ctx[i] = cc[ids[b] * 32 + (i & 31)];
    }
    for (int i = t; i < BATCH * CH * 16 * 16; i += T) {
        int b = i >> 11;
        g_xA[i] = lat[ids[b] * (CH * 16 * 16) + (i & 2047)];
    }
}

// ---------------- dynamic weight computation ----------------
// grid: (13 instances, 64 batch); 128 threads
// inst 0..3: r(3x3) stage; 4..7: t(4x4); 8..11: m(5x5); 12: final(1x1, O=3)
__global__ void k_weights(
    const float* __restrict__ Wr, const float* __restrict__ Ur, const float* __restrict__ Vr, const float* __restrict__ Br,
    const float* __restrict__ Wt, const float* __restrict__ Ut, const float* __restrict__ Vt, const float* __restrict__ Bt,
    const float* __restrict__ Wm, const float* __restrict__ Um, const float* __restrict__ Vm, const float* __restrict__ Bm,
    const float* __restrict__ Wo, const float* __restrict__ Uo, const float* __restrict__ Vo, const float* __restrict__ Bo)
{
    int inst = blockIdx.x, b = blockIdx.y, tid = threadIdx.x;
    __shared__ float sctx[32];
    __shared__ float su[128];
    __shared__ float sv[3200];
    if (tid < 32) sctx[tid] = g_ctx[b * 32 + tid];
    __syncthreads();

    int O, KK;
    const float *U, *V, *W, *Bb;
    float *gw, *gb;
    if (inst < 12) {
        int type = inst >> 2, stage = inst & 3;
        O = CH;
        if (type == 0)      { KK = 9;  U = Ur; V = Vr; W = Wr; Bb = Br; gw = g_wr; gb = g_br; }
        else if (type == 1) { KK = 16; U = Ut; V = Vt; W = Wt; Bb = Bt; gw = g_wt; gb = g_bt; }
        else                { KK = 25; U = Um; V = Vm; W = Wm; Bb = Bm; gw = g_wm; gb = g_bm; }
        int uLen = 16 * O, vLen = 16 * CH * KK;
        U  += (size_t)stage * 32 * uLen;
        V  += (size_t)stage * 32 * vLen;
        W  += (size_t)stage * O * CH * KK;
        Bb += (size_t)stage * 32 * O;
        gw += (size_t)(stage * BATCH + b) * O * CH * KK;
        gb += (size_t)(stage * BATCH + b) * O;
    } else {
        O = 3; KK = 1;
        U = Uo; V = Vo; W = Wo; Bb = Bo;
        gw = g_wo + b * 3 * CH;
        gb = g_bo + b * 3;
    }
    int uLen = 16 * O, vLen = 16 * CH * KK, IKK = CH * KK, wN = O * IKK;

    for (int j = tid; j < uLen; j += blockDim.x) {
        float s = 0.f;
        #pragma unroll
        for (int l = 0; l < 32; l++) s += sctx[l] * U[l * uLen + j];
        su[j] = s;
    }
    for (int j = tid; j < vLen; j += blockDim.x) {
        float s = 0.f;
        #pragma unroll
        for (int l = 0; l < 32; l++) s += sctx[l] * V[l * vLen + j];
        sv[j] = s;
    }
    __syncthreads();

    for (int widx = tid; widx < wN; widx += blockDim.x) {
        int o = widx / IKK, k = widx - o * IKK;
        float m = 0.f;
        #pragma unroll
        for (int r = 0; r < 16; r++) m += su[r * O + o] * sv[r * IKK + k];
        gw[widx] = W[widx] * (1.0f + m + 1e-3f);
    }
    if (tid < O) {
        float s = 0.f;
        #pragma unroll
        for (int l = 0; l < 32; l++) s += sctx[l] * Bb[l * O + tid];
        gb[tid] = s;
    }
}

// ---------------- conv 3x3 stride1 pad1 (per-sample weights) ----------------
// one block per (b,o) map, 256 threads; writes g_pos + per-map min
__global__ __launch_bounds__(256) void k_conv3(int logH, int stage, int srcA) {
    const float* x = srcA ? g_xA : g_xB;
    int H = 1 << logH;
    int bo = blockIdx.x, b = bo >> 3, o = bo & 7, tid = threadIdx.x;
    __shared__ float sw[72];
    __shared__ float sbias;
    if (tid < 72) sw[tid] = g_wr[(stage * BATCH + b) * (CH * CH * 9) + o * 72 + tid];
    if (tid == 0) sbias = g_br[(stage * BATCH + b) * CH + o];
    __syncthreads();
    int N = H * H;
    const float* xb = x + (size_t)b * CH * N;
    float* out = g_pos + (size_t)bo * N;
    float bias = sbias;
    float mn = 3.4e38f;
    for (int p = tid; p < N; p += 256) {
        int oy = p >> logH, ox = p & (H - 1);
        float acc = bias;
        #pragma unroll
        for (int i = 0; i < CH; i++) {
            const float* xi = xb + i * N;
            #pragma unroll
            for (int ky = 0; ky < 3; ky++) {
                int yy = oy + ky - 1;
                if ((unsigned)yy >= (unsigned)H) continue;
                #pragma unroll
                for (int kx = 0; kx < 3; kx++) {
                    int xx = ox + kx - 1;
                    if ((unsigned)xx >= (unsigned)H) continue;
                    acc += xi[yy * H + xx] * sw[i * 9 + ky * 3 + kx];
                }
            }
        }
        out[p] = acc;
        mn = fminf(mn, fabsf(acc));
    }
    block_min_write<256>(mn, &g_minpos[bo]);
}

// ---------------- convT 4x4 stride2 pad1 on -x ----------------
__global__ __launch_bounds__(256) void k_convt(int logH, int stage, int srcA) {
    const float* x = srcA ? g_xA : g_xB;
    int H = 1 << logH, OH = 2 * H;
    int bo = blockIdx.x, b = bo >> 3, o = bo & 7, tid = threadIdx.x;
    __shared__ float sw[128];
    __shared__ float sbias;
    for (int j = tid; j < 128; j += 256)
        sw[j] = g_wt[(stage * BATCH + b) * (CH * CH * 16) + o * 128 + j];
    if (tid == 0) sbias = g_bt[(stage * BATCH + b) * CH + o];
    __syncthreads();
    int N = H * H, NO = OH * OH;
    const float* xb = x + (size_t)b * CH * N;
    float* out = g_neg + (size_t)bo * NO;
    float bias = sbias;
    float mn = 3.4e38f;
    for (int p = tid; p < NO; p += 256) {
        int oy = p >> (logH + 1), ox = p & (OH - 1);
        float acc = bias;
        #pragma unroll
        for (int ky = 0; ky < 4; ky++) {
            int dy = oy - 2 + ky;
            if (dy & 1) continue;
            int iy = dy >> 1;
            if ((unsigned)iy >= (unsigned)H) continue;
            #pragma unroll
            for (int kx = 0; kx < 4; kx++) {
                int dx = ox - 2 + kx;
                if (dx & 1) continue;
                int ix = dx >> 1;
                if ((unsigned)ix >= (unsigned)H) continue;
                int wb = (3 - ky) * 4 + (3 - kx);
                #pragma unroll
                for (int i = 0; i < CH; i++)
                    acc -= xb[i * N + iy * H + ix] * sw[i * 16 + wb];  // input is -x
            }
        }
        out[p] = acc;
        mn = fminf(mn, fabsf(acc));
    }
    block_min_write<256>(mn, &g_minneg[bo]);
}

// ---------------- lx = log(|x|+1) ----------------
__global__ void k_lx(int N, int srcA) {
    const float* x = srcA ? g_xA : g_xB;
    int t = blockIdx.x * blockDim.x + threadIdx.x;
    if (t < N) g_lx[t] = logf(fabsf(x[t]) + 1.0f);
}

// ---------------- exact 2x bilinear (jax.image.resize semantics) ----------------
__global__ void k_xu(int logH) {
    int H = 1 << logH, OH = 2 * H;
    int NO = OH * OH;
    int total = BATCH * CH * NO;
    int t = blockIdx.x * blockDim.x + threadIdx.x;
    if (t >= total) return;
    int bc = t / NO, r = t - bc * NO;
    int Y = r >> (logH + 1), X = r & (OH - 1);
    const float* lx = g_lx + (size_t)bc * H * H;
    int iy = Y >> 1, ix = X >> 1;
    int yo = (Y & 1) ? min(iy + 1, H - 1) : max(iy - 1, 0);
    int xo = (X & 1) ? min(ix + 1, H - 1) : max(ix - 1, 0);
    float v = 0.5625f * lx[iy * H + ix] + 0.1875f * lx[iy * H + xo]
            + 0.1875f * lx[yo * H + ix] + 0.0625f * lx[yo * H + xo];
    g_xu[t] = v;
}

// ---------------- conv 5x5 stride1 pad2 over g_xu (OHxOH) ----------------
__global__ __launch_bounds__(512) void k_conv5(int logH, int stage) {
    int H = 1 << logH, OH = 2 * H;
    int bo = blockIdx.x, b = bo >> 3, o = bo & 7, tid = threadIdx.x;
    __shared__ float sw[200];
    __shared__ float sbias;
    for (int j = tid; j < 200; j += 512)
        sw[j] = g_wm[(stage * BATCH + b) * (CH * CH * 25) + o * 200 + j];
    if (tid == 0) sbias = g_bm[(stage * BATCH + b) * CH + o];
    __syncthreads();
    int NO = OH * OH;
    const float* xb = g_xu + (size_t)b * CH * NO;
    float* out = g_mul + (size_t)bo * NO;
    float bias = sbias;
    float mn = 3.4e38f;
    for (int p = tid; p < NO; p += 512) {
        int oy = p >> (logH + 1), ox = p & (OH - 1);
        float acc = bias;
        if (oy >= 2 && oy < OH - 2 && ox >= 2 && ox < OH - 2) {
            const float* base = xb + (oy - 2) * OH + (ox - 2);
            #pragma unroll
            for (int i = 0; i < CH; i++) {
                const float* xi = base + i * NO;
                #pragma unroll
                for (int ky = 0; ky < 5; ky++)
                    #pragma unroll
                    for (int kx = 0; kx < 5; kx++)
                        acc += xi[ky * OH + kx] * sw[i * 25 + ky * 5 + kx];
            }
        } else {
            for (int i = 0; i < CH; i++) {
                const float* xi = xb + i * NO;
                #pragma unroll
                for (int ky = 0; ky < 5; ky++) {
                    int yy = oy + ky - 2;
                    if ((unsigned)yy >= (unsigned)OH) continue;
                    #pragma unroll
                    for (int kx = 0; kx < 5; kx++) {
                        int xx = ox + kx - 2;
                        if ((unsigned)xx >= (unsigned)OH) continue;
                        acc += xi[yy * OH + xx] * sw[i * 25 + ky * 5 + kx];
                    }
                }
            }
        }
        out[p] = acc;
        mn = fminf(mn, fabsf(acc));
    }
    block_min_write<512>(mn, &g_minmul[bo]);
}

// ---------------- combine: (up_nearest(dln(pos)) + dln(neg)) * dln(mul) ----------------
__global__ void k_combine(int logH, int dstA) {
    int H = 1 << logH, OH = 2 * H;
    float* dst = dstA ? g_xA : g_xB;
    int NO = OH * OH;
    int total = BATCH * CH * NO;
    int t = blockIdx.x * blockDim.x + threadIdx.x;
    if (t >= total) return;
    int bc = t / NO, r = t - bc * NO;
    int Y = r >> (logH + 1), X = r & (OH - 1);
    float vp = g_pos[(size_t)bc * H * H + (Y >> 1) * H + (X >> 1)];
    float dp = dln_f(vp, g_minpos[bc]);
    float dn = dln_f(g_neg[t], g_minneg[bc]);
    float dm = dln_f(g_mul[t], g_minmul[bc]);
    dst[t] = (dp + dn) * dm;
}

// ---------------- final dynamic 1x1 conv -> 3 channels ----------------
__global__ void k_final(int srcA, float* __restrict__ out) {
    const float* x = srcA ? g_xA : g_xB;
    const int NP = 256 * 256;
    int total = BATCH * 3 * NP;
    int t = blockIdx.x * blockDim.x + threadIdx.x;
    if (t >= total) return;
    int b = t / (3 * NP);
    int r = t - b * 3 * NP;
    int o = r / NP, pix = r - o * NP;
    const float* xb = x + (size_t)b * CH * NP;
    float acc = g_bo[b * 3 + o];
    #pragma unroll
    for (int i = 0; i < CH; i++)
        acc += g_wo[b * 24 + o * 8 + i] * xb[i * NP + pix];
    out[t] = acc;
}

// ---------------- launcher ----------------
extern "C" void kernel_launch(void* const* d_in, const int* in_sizes, int n_in,
                              void* d_out, int out_size) {
    const int*   ids = (const int*)  d_in[0];
    const float* cc  = (const float*)d_in[1];
    const float* lat = (const float*)d_in[2];
    const float* Wr = (const float*)d_in[3];
    const float* Ur = (const float*)d_in[4];
    const float* Vr = (const float*)d_in[5];
    const float* Br = (const float*)d_in[6];
    const float* Wt = (const float*)d_in[7];
    const float* Ut = (const float*)d_in[8];
    const float* Vt = (const float*)d_in[9];
    const float* Bt = (const float*)d_in[10];
    const float* Wm = (const float*)d_in[11];
    const float* Um = (const float*)d_in[12];
    const float* Vm = (const float*)d_in[13];
    const float* Bm = (const float*)d_in[14];
    const float* Wo = (const float*)d_in[15];
    const float* Uo = (const float*)d_in[16];
    const float* Vo = (const float*)d_in[17];
    const float* Bo = (const float*)d_in[18];

    k_gather<<<64, 256>>>(ids, cc, lat);
    k_weights<<<dim3(13, 64), 128>>>(Wr, Ur, Vr, Br, Wt, Ut, Vt, Bt,
                                     Wm, Um, Vm, Bm, Wo, Uo, Vo, Bo);
    int srcA = 1;
    for (int s = 0; s < 4; s++) {
        int logH = 4 + s;
        int H = 1 << logH, OH = 2 * H;
        int Nlx = BATCH * CH * H * H;
        int Nout = BATCH * CH * OH * OH;
        k_conv3<<<BATCH * CH, 256>>>(logH, s, srcA);
        k_convt<<<BATCH * CH, 256>>>(logH, s, srcA);
        k_lx<<<(Nlx + 255) / 256, 256>>>(Nlx, srcA);
        k_xu<<<(Nout + 255) / 256, 256>>>(logH);
        k_conv5<<<BATCH * CH, 512>>>(logH, s);
        k_combine<<<(Nout + 255) / 256, 256>>>(logH, srcA ^ 1);
        srcA ^= 1;
    }
    k_final<<<(BATCH * 3 * 256 * 256 + 255) / 256, 256>>>(srcA, (float*)d_out);
}

// round 2
// speedup vs baseline: 8.4174x; 8.4174x over previous
#include <cuda_runtime.h>
#include <cuda_bf16.h>

#define BATCH 64
#define CH 8
#define NSTAGE 4

// ---------------- device scratch (static, no allocations) ----------------
__device__ float g_ctx[BATCH*32];
__device__ float g_wr[NSTAGE*BATCH*CH*CH*9];
__device__ float g_wt[NSTAGE*BATCH*CH*CH*16];
__device__ float g_wm[NSTAGE*BATCH*CH*CH*25];
__device__ float g_wo[BATCH*3*CH];
__device__ float g_br[NSTAGE*BATCH*CH];
__device__ float g_bt[NSTAGE*BATCH*CH];
__device__ float g_bm[NSTAGE*BATCH*CH];
__device__ float g_bo[BATCH*3];
__device__ float g_xA[BATCH*CH*256*256];
__device__ float g_xB[BATCH*CH*256*256];
__device__ float g_pos[BATCH*CH*128*128];
__device__ float g_neg[BATCH*CH*256*256];
__device__ float g_mul[BATCH*CH*256*256];
__device__ float g_lx[BATCH*CH*128*128];
__device__ float g_xu[BATCH*CH*256*256];
__device__ unsigned g_minpos[BATCH*CH];
__device__ unsigned g_minneg[BATCH*CH];
__device__ unsigned g_minmul[BATCH*CH];

__device__ __forceinline__ float dln_f(float v, float mn) {
    float s = (v > 0.0f) ? 1.0f : -1.0f;
    float a = fabsf(v) - mn;
    return s * logf(logf(a + 2.718281828459045f) + 0.01f);
}

// ---------------- gather: ctx + initial x ----------------
__global__ void k_gather(const int* __restrict__ ids,
                         const float* __restrict__ cc,
                         const float* __restrict__ lat) {
    int t = blockIdx.x * blockDim.x + threadIdx.x;
    int T = gridDim.x * blockDim.x;
    for (int i = t; i < BATCH * 32; i += T) {
        int b = i >> 5;
        g_ctx[i] = cc[ids[b] * 32 + (i & 31)];
    }
    for (int i = t; i < BATCH * CH * 16 * 16; i += T) {
        int b = i >> 11;
        g_xA[i] = lat[ids[b] * (CH * 16 * 16) + (i & 2047)];
    }
}

// ---------------- min init ----------------
__global__ void k_mininit() {
    int t = blockIdx.x * blockDim.x + threadIdx.x;
    if (t < BATCH * CH) {
        g_minpos[t] = 0x7F800000u;
        g_minneg[t] = 0x7F800000u;
        g_minmul[t] = 0x7F800000u;
    }
}

// ---------------- dynamic weight computation ----------------
__global__ void k_weights(
    const float* __restrict__ Wr, const float* __restrict__ Ur, const float* __restrict__ Vr, const float* __restrict__ Br,
    const float* __restrict__ Wt, const float* __restrict__ Ut, const float* __restrict__ Vt, const float* __restrict__ Bt,
    const float* __restrict__ Wm, const float* __restrict__ Um, const float* __restrict__ Vm, const float* __restrict__ Bm,
    const float* __restrict__ Wo, const float* __restrict__ Uo, const float* __restrict__ Vo, const float* __restrict__ Bo)
{
    int inst = blockIdx.x, b = blockIdx.y, tid = threadIdx.x;
    __shared__ float sctx[32];
    __shared__ float su[128];
    __shared__ float sv[3200];
    if (tid < 32) sctx[tid] = g_ctx[b * 32 + tid];
    __syncthreads();

    int O, KK;
    const float *U, *V, *W, *Bb;
    float *gw, *gb;
    if (inst < 12) {
        int type = inst >> 2, stage = inst & 3;
        O = CH;
        if (type == 0)      { KK = 9;  U = Ur; V = Vr; W = Wr; Bb = Br; gw = g_wr; gb = g_br; }
        else if (type == 1) { KK = 16; U = Ut; V = Vt; W = Wt; Bb = Bt; gw = g_wt; gb = g_bt; }
        else                { KK = 25; U = Um; V = Vm; W = Wm; Bb = Bm; gw = g_wm; gb = g_bm; }
        int uLen = 16 * O, vLen = 16 * CH * KK;
        U  += (size_t)stage * 32 * uLen;
        V  += (size_t)stage * 32 * vLen;
        W  += (size_t)stage * O * CH * KK;
        Bb += (size_t)stage * 32 * O;
        gw += (size_t)(stage * BATCH + b) * O * CH * KK;
        gb += (size_t)(stage * BATCH + b) * O;
    } else {
        O = 3; KK = 1;
        U = Uo; V = Vo; W = Wo; Bb = Bo;
        gw = g_wo + b * 3 * CH;
        gb = g_bo + b * 3;
    }
    int uLen = 16 * O, vLen = 16 * CH * KK, IKK = CH * KK, wN = O * IKK;

    for (int j = tid; j < uLen; j += blockDim.x) {
        float s = 0.f;
        #pragma unroll
        for (int l = 0; l < 32; l++) s += sctx[l] * U[l * uLen + j];
        su[j] = s;
    }
    for (int j = tid; j < vLen; j += blockDim.x) {
        float s = 0.f;
        #pragma unroll
        for (int l = 0; l < 32; l++) s += sctx[l] * V[l * vLen + j];
        sv[j] = s;
    }
    __syncthreads();

    for (int widx = tid; widx < wN; widx += blockDim.x) {
        int o = widx / IKK, k = widx - o * IKK;
        float m = 0.f;
        #pragma unroll
        for (int r = 0; r < 16; r++) m += su[r * O + o] * sv[r * IKK + k];
        gw[widx] = W[widx] * (1.0f + m + 1e-3f);
    }
    if (tid < O) {
        float s = 0.f;
        #pragma unroll
        for (int l = 0; l < 32; l++) s += sctx[l] * Bb[l * O + tid];
        gb[tid] = s;
    }
}

// ---------------- generic tiled conv (KS=3 pad1 / KS=5 pad2) ----------------
// block: TW x TH pixel tile, all CH output channels of one sample
// threads = TW*8; thread (tx, o) computes TH pixels in y
// WHICH: 0 = conv3 (x -> g_pos), 1 = conv5 (g_xu -> g_mul)
template<int HH, int KS, int TW, int TH, int WHICH>
__global__ __launch_bounds__(TW*CH) void k_convG(int stage, int srcA) {
    constexpr int PAD = KS / 2;
    constexpr int IW = TW + KS - 1;
    constexpr int IH = TH + KS - 1;
    constexpr int KK = KS * KS;
    constexpr int NT = TW * CH;
    __shared__ float sIn[CH][IH][IW];
    __shared__ float sW[CH * CH * KK];
    __shared__ float sB[CH];

    int b = blockIdx.z;
    int x0 = blockIdx.x * TW, y0 = blockIdx.y * TH;
    int tid = threadIdx.x;

    const float* xin;
    const float* wsrc;
    const float* bsrc;
    float* out;
    unsigned* gmin;
    if (WHICH == 0) {
        xin = srcA ? g_xA : g_xB;
        wsrc = g_wr + (size_t)(stage * BATCH + b) * CH * CH * KK;
        bsrc = g_br + (size_t)(stage * BATCH + b) * CH;
        out = g_pos; gmin = g_minpos;
    } else {
        xin = g_xu;
        wsrc = g_wm + (size_t)(stage * BATCH + b) * CH * CH * KK;
        bsrc = g_bm + (size_t)(stage * BATCH + b) * CH;
        out = g_mul; gmin = g_minmul;
    }
    const float* xb = xin + (size_t)b * CH * HH * HH;

    for (int j = tid; j < CH * CH * KK; j += NT) sW[j] = wsrc[j];
    if (tid < CH) sB[tid] = bsrc[tid];
    #pragma unroll 2
    for (int j = tid; j < CH * IH * IW; j += NT) {
        int i = j / (IH * IW);
        int rem = j - i * IH * IW;
        int r = rem / IW, c = rem - r * IW;
        int gy = y0 - PAD + r, gx = x0 - PAD + c;
        float v = 0.f;
        if ((unsigned)gy < (unsigned)HH && (unsigned)gx < (unsigned)HH)
            v = xb[i * HH * HH + gy * HH + gx];
        sIn[i][r][c] = v;
    }
    __syncthreads();

    int tx = tid & (TW - 1);
    int o  = tid / TW;
    float acc[TH];
    float bias = sB[o];
    #pragma unroll
    for (int y = 0; y < TH; y++) acc[y] = bias;

    #pragma unroll
    for (int i = 0; i < CH; i++) {
        float w[KK];
        #pragma unroll
        for (int k = 0; k < KK; k++) w[k] = sW[(o * CH + i) * KK + k];
        #pragma unroll
        for (int r = 0; r < IH; r++) {
            float v[KS];
            #pragma unroll
            for (int k = 0; k < KS; k++) v[k] = sIn[i][r][tx + k];
            #pragma unroll
            for (int ky = 0; ky < KS; ky++) {
                int y = r - ky;
                if (y >= 0 && y < TH) {
                    #pragma unroll
                    for (int kx = 0; kx < KS; kx++)
                        acc[y] += v[kx] * w[ky * KS + kx];
                }
            }
        }
    }

    int bo = b * CH + o;
    float* outp = out + (size_t)bo * HH * HH;
    float mn = 3.4e38f;
    #pragma unroll
    for (int y = 0; y < TH; y++) {
        outp[(y0 + y) * HH + x0 + tx] = acc[y];
        mn = fminf(mn, fabsf(acc[y]));
    }
    #pragma unroll
    for (int off = TW / 2; off > 0; off >>= 1)
        mn = fminf(mn, __shfl_down_sync(0xFFFFFFFFu, mn, off, TW));
    if (tx == 0) atomicMin(&gmin[bo], __float_as_uint(mn));
}

// ---------------- convT 4x4 stride2 pad1 on -x (parity-decomposed) ----------------
template<int HH>
__global__ __launch_bounds__(256) void k_convtG(int stage, int srcA) {
    constexpr int OH = 2 * HH;
    constexpr int TW = 32, TH = 8;
    constexpr int IWT = TW / 2 + 2;   // 18
    constexpr int IHT = TH / 2 + 2;   // 6
    __shared__ float sIn[CH][IHT][IWT];
    __shared__ float sW[CH * CH * 16];
    __shared__ float sB[CH];

    int b = blockIdx.z;
    int x0 = blockIdx.x * TW, y0 = blockIdx.y * TH;
    int tid = threadIdx.x;
    const float* x = (srcA ? g_xA : g_xB) + (size_t)b * CH * HH * HH;
    const float* wsrc = g_wt + (size_t)(stage * BATCH + b) * CH * CH * 16;
    if (tid < CH) sB[tid] = g_bt[(stage * BATCH + b) * CH + tid];
    for (int j = tid; j < CH * CH * 16; j += 256) sW[j] = wsrc[j];
    int ix0 = x0 / 2 - 1, iy0 = y0 / 2 - 1;
    for (int j = tid; j < CH * IHT * IWT; j += 256) {
        int i = j / (IHT * IWT);
        int rem = j - i * IHT * IWT;
        int r = rem / IWT, c = rem - r * IWT;
        int gy = iy0 + r, gx = ix0 + c;
        float v = 0.f;
        if ((unsigned)gy < (unsigned)HH && (unsigned)gx < (unsigned)HH)
            v = x[i * HH * HH + gy * HH + gx];
        sIn[i][r][c] = v;
    }
    __syncthreads();

    int tx = tid & 31, o = tid >> 5;
    int px = tx & 1;
    int cA = (tx >> 1) + px;
    float acc[TH];
    float bias = sB[o];
    #pragma unroll
    for (int y = 0; y < TH; y++) acc[y] = bias;

    #pragma unroll
    for (int i = 0; i < CH; i++) {
        float wA[4], wB[4];
        #pragma unroll
        for (int ky = 0; ky < 4; ky++) {
            wA[ky] = sW[(o * CH + i) * 16 + ky * 4 + (3 - px)];
            wB[ky] = sW[(o * CH + i) * 16 + ky * 4 + (1 - px)];
        }
        float vA[IHT], vB[IHT];
        #pragma unroll
        for (int r = 0; r < IHT; r++) {
            vA[r] = sIn[i][r][cA];
            vB[r] = sIn[i][r][cA + 1];
        }
        #pragma unroll
        for (int ty = 0; ty < TH; ty++) {
            const int py = ty & 1;
            const int r = (ty >> 1) + py;
            acc[ty] -= vA[r]     * wA[3 - py]
                     + vB[r]     * wB[3 - py]
                     + vA[r + 1] * wA[1 - py]
                     + vB[r + 1] * wB[1 - py];
        }
    }

    int bo = b * CH + o;
    float* outp = g_neg + (size_t)bo * OH * OH;
    float mn = 3.4e38f;
    #pragma unroll
    for (int y = 0; y < TH; y++) {
        outp[(y0 + y) * OH + x0 + tx] = acc[y];
        mn = fminf(mn, fabsf(acc[y]));
    }
    #pragma unroll
    for (int off = 16; off > 0; off >>= 1)
        mn = fminf(mn, __shfl_down_sync(0xFFFFFFFFu, mn, off));
    if (tx == 0) atomicMin(&g_minneg[bo], __float_as_uint(mn));
}

// ---------------- lx = log(|x|+1) ----------------
__global__ void k_lx(int N, int srcA) {
    const float* x = srcA ? g_xA : g_xB;
    int t = blockIdx.x * blockDim.x + threadIdx.x;
    if (t < N) g_lx[t] = logf(fabsf(x[t]) + 1.0f);
}

// ---------------- exact 2x bilinear (jax.image.resize semantics) ----------------
__global__ void k_xu(int logH) {
    int H = 1 << logH, OH = 2 * H;
    int NO = OH * OH;
    int total = BATCH * CH * NO;
    int t = blockIdx.x * blockDim.x + threadIdx.x;
    if (t >= total) return;
    int bc = t / NO, r = t - bc * NO;
    int Y = r >> (logH + 1), X = r & (OH - 1);
    const float* lx = g_lx + (size_t)bc * H * H;
    int iy = Y >> 1, ix = X >> 1;
    int yo = (Y & 1) ? min(iy + 1, H - 1) : max(iy - 1, 0);
    int xo = (X & 1) ? min(ix + 1, H - 1) : max(ix - 1, 0);
    float v = 0.5625f * lx[iy * H + ix] + 0.1875f * lx[iy * H + xo]
            + 0.1875f * lx[yo * H + ix] + 0.0625f * lx[yo * H + xo];
    g_xu[t] = v;
}

// ---------------- combine: (up_nearest(dln(pos)) + dln(neg)) * dln(mul) ----------------
__global__ void k_combine(int logH, int dstA) {
    int H = 1 << logH, OH = 2 * H;
    float* dst = dstA ? g_xA : g_xB;
    int NO = OH * OH;
    int total = BATCH * CH * NO;
    int t = blockIdx.x * blockDim.x + threadIdx.x;
    if (t >= total) return;
    int bc = t / NO, r = t - bc * NO;
    int Y = r >> (logH + 1), X = r & (OH - 1);
    float vp = g_pos[(size_t)bc * H * H + (Y >> 1) * H + (X >> 1)];
    float dp = dln_f(vp, __uint_as_float(g_minpos[bc]));
    float dn = dln_f(g_neg[t], __uint_as_float(g_minneg[bc]));
    float dm = dln_f(g_mul[t], __uint_as_float(g_minmul[bc]));
    dst[t] = (dp + dn) * dm;
}

// ---------------- final dynamic 1x1 conv -> 3 channels ----------------
__global__ void k_final(int srcA, float* __restrict__ out) {
    const float* x = srcA ? g_xA : g_xB;
    const int NP = 256 * 256;
    int t = blockIdx.x * blockDim.x + threadIdx.x;
    if (t >= BATCH * NP) return;
    int b = t / NP, pix = t - b * NP;
    const float* xb = x + (size_t)b * CH * NP;
    float vin[CH];
    #pragma unroll
    for (int i = 0; i < CH; i++) vin[i] = xb[i * NP + pix];
    #pragma unroll
    for (int o = 0; o < 3; o++) {
        float acc = g_bo[b * 3 + o];
        #pragma unroll
        for (int i = 0; i < CH; i++) acc += g_wo[b * 24 + o * 8 + i] * vin[i];
        out[((size_t)b * 3 + o) * NP + pix] = acc;
    }
}

// ---------------- launcher ----------------
extern "C" void kernel_launch(void* const* d_in, const int* in_sizes, int n_in,
                              void* d_out, int out_size) {
    const int*   ids = (const int*)  d_in[0];
    const float* cc  = (const float*)d_in[1];
    const float* lat = (const float*)d_in[2];
    const float* Wr = (const float*)d_in[3];
    const float* Ur = (const float*)d_in[4];
    const float* Vr = (const float*)d_in[5];
    const float* Br = (const float*)d_in[6];
    const float* Wt = (const float*)d_in[7];
    const float* Ut = (const float*)d_in[8];
    const float* Vt = (const float*)d_in[9];
    const float* Bt = (const float*)d_in[10];
    const float* Wm = (const float*)d_in[11];
    const float* Um = (const float*)d_in[12];
    const float* Vm = (const float*)d_in[13];
    const float* Bm = (const float*)d_in[14];
    const float* Wo = (const float*)d_in[15];
    const float* Uo = (const float*)d_in[16];
    const float* Vo = (const float*)d_in[17];
    const float* Bo = (const float*)d_in[18];

    k_gather<<<64, 256>>>(ids, cc, lat);
    k_weights<<<dim3(13, 64), 128>>>(Wr, Ur, Vr, Br, Wt, Ut, Vt, Bt,
                                     Wm, Um, Vm, Bm, Wo, Uo, Vo, Bo);
    int srcA = 1;
    for (int s = 0; s < 4; s++) {
        int logH = 4 + s;
        int H = 1 << logH, OH = 2 * H;
        int Nlx = BATCH * CH * H * H;
        int Nout = BATCH * CH * OH * OH;

        k_mininit<<<2, 256>>>();

        // conv3 at H
        switch (s) {
            case 0: k_convG<16, 3, 16, 8, 0><<<dim3(1, 2, BATCH), 128>>>(s, srcA); break;
            case 1: k_convG<32, 3, 32, 8, 0><<<dim3(1, 4, BATCH), 256>>>(s, srcA); break;
            case 2: k_convG<64, 3, 32, 8, 0><<<dim3(2, 8, BATCH), 256>>>(s, srcA); break;
            case 3: k_convG<128, 3, 32, 8, 0><<<dim3(4, 16, BATCH), 256>>>(s, srcA); break;
        }
        // convT: output at OH
        switch (s) {
            case 0: k_convtG<16><<<dim3(1, 4, BATCH), 256>>>(s, srcA); break;
            case 1: k_convtG<32><<<dim3(2, 8, BATCH), 256>>>(s, srcA); break;
            case 2: k_convtG<64><<<dim3(4, 16, BATCH), 256>>>(s, srcA); break;
            case 3: k_convtG<128><<<dim3(8, 32, BATCH), 256>>>(s, srcA); break;
        }
        // lx + bilinear upsample
        k_lx<<<(Nlx + 255) / 256, 256>>>(Nlx, srcA);
        k_xu<<<(Nout + 255) / 256, 256>>>(logH);
        // conv5 at OH
        switch (s) {
            case 0: k_convG<32, 5, 32, 8, 1><<<dim3(1, 4, BATCH), 256>>>(s, 0); break;
            case 1: k_convG<64, 5, 32, 8, 1><<<dim3(2, 8, BATCH), 256>>>(s, 0); break;
            case 2: k_convG<128, 5, 32, 8, 1><<<dim3(4, 16, BATCH), 256>>>(s, 0); break;
            case 3: k_convG<256, 5, 32, 8, 1><<<dim3(8, 32, BATCH), 256>>>(s, 0); break;
        }
        // combine
        k_combine<<<(Nout + 255) / 256, 256>>>(logH, srcA ^ 1);
        srcA ^= 1;
    }
    k_final<<<(BATCH * 256 * 256 + 255) / 256, 256>>>(srcA, (float*)d_out);
}

// round 3
// speedup vs baseline: 10.9928x; 1.3060x over previous
#include <cuda_runtime.h>
#include <cuda_bf16.h>

#define BATCH 64
#define CH 8
#define NSTAGE 4

// ---------------- device scratch (static, no allocations) ----------------
__device__ float g_ctx[BATCH*32];
__device__ float g_wr[NSTAGE*BATCH*CH*CH*9];
__device__ float g_wt[NSTAGE*BATCH*CH*CH*16];
__device__ float g_wm[NSTAGE*BATCH*CH*CH*25];
__device__ float g_wo[BATCH*3*CH];
__device__ float g_br[NSTAGE*BATCH*CH];
__device__ float g_bt[NSTAGE*BATCH*CH];
__device__ float g_bm[NSTAGE*BATCH*CH];
__device__ float g_bo[BATCH*3];
__device__ float g_xA[BATCH*CH*128*128];
__device__ float g_xB[BATCH*CH*128*128];
__device__ float g_pos[BATCH*CH*128*128];
__device__ float g_neg[BATCH*CH*256*256];
__device__ float g_mul[BATCH*CH*256*256];
__device__ unsigned g_minpos[NSTAGE*BATCH*CH];
__device__ unsigned g_minneg[NSTAGE*BATCH*CH];
__device__ unsigned g_minmul[NSTAGE*BATCH*CH];

__device__ __forceinline__ float dln_f(float v, float mn) {
    float s = (v > 0.0f) ? 1.0f : -1.0f;
    float a = fabsf(v) - mn;
    return s * __logf(__logf(a + 2.718281828459045f) + 0.01f);
}

// ---------------- gather: ctx + initial x ----------------
__global__ void k_gather(const int* __restrict__ ids,
                         const float* __restrict__ cc,
                         const float* __restrict__ lat) {
    int t = blockIdx.x * blockDim.x + threadIdx.x;
    int T = gridDim.x * blockDim.x;
    for (int i = t; i < BATCH * 32; i += T) {
        int b = i >> 5;
        g_ctx[i] = cc[ids[b] * 32 + (i & 31)];
    }
    for (int i = t; i < BATCH * CH * 16 * 16; i += T) {
        int b = i >> 11;
        g_xA[i] = lat[ids[b] * (CH * 16 * 16) + (i & 2047)];
    }
}

// ---------------- min init (all stages at once) ----------------
__global__ void k_mininit() {
    int t = blockIdx.x * blockDim.x + threadIdx.x;
    if (t < NSTAGE * BATCH * CH) {
        g_minpos[t] = 0x7F800000u;
        g_minneg[t] = 0x7F800000u;
        g_minmul[t] = 0x7F800000u;
    }
}

// ---------------- dynamic weight computation ----------------
__global__ void k_weights(
    const float* __restrict__ Wr, const float* __restrict__ Ur, const float* __restrict__ Vr, const float* __restrict__ Br,
    const float* __restrict__ Wt, const float* __restrict__ Ut, const float* __restrict__ Vt, const float* __restrict__ Bt,
    const float* __restrict__ Wm, const float* __restrict__ Um, const float* __restrict__ Vm, const float* __restrict__ Bm,
    const float* __restrict__ Wo, const float* __restrict__ Uo, const float* __restrict__ Vo, const float* __restrict__ Bo)
{
    int inst = blockIdx.x, b = blockIdx.y, tid = threadIdx.x;
    __shared__ float sctx[32];
    __shared__ float su[128];
    __shared__ float sv[3200];
    if (tid < 32) sctx[tid] = g_ctx[b * 32 + tid];
    __syncthreads();

    int O, KK;
    const float *U, *V, *W, *Bb;
    float *gw, *gb;
    if (inst < 12) {
        int type = inst >> 2, stage = inst & 3;
        O = CH;
        if (type == 0)      { KK = 9;  U = Ur; V = Vr; W = Wr; Bb = Br; gw = g_wr; gb = g_br; }
        else if (type == 1) { KK = 16; U = Ut; V = Vt; W = Wt; Bb = Bt; gw = g_wt; gb = g_bt; }
        else                { KK = 25; U = Um; V = Vm; W = Wm; Bb = Bm; gw = g_wm; gb = g_bm; }
        int uLen = 16 * O, vLen = 16 * CH * KK;
        U  += (size_t)stage * 32 * uLen;
        V  += (size_t)stage * 32 * vLen;
        W  += (size_t)stage * O * CH * KK;
        Bb += (size_t)stage * 32 * O;
        gw += (size_t)(stage * BATCH + b) * O * CH * KK;
        gb += (size_t)(stage * BATCH + b) * O;
    } else {
        O = 3; KK = 1;
        U = Uo; V = Vo; W = Wo; Bb = Bo;
        gw = g_wo + b * 3 * CH;
        gb = g_bo + b * 3;
    }
    int uLen = 16 * O, vLen = 16 * CH * KK, IKK = CH * KK, wN = O * IKK;

    for (int j = tid; j < uLen; j += blockDim.x) {
        float s = 0.f;
        #pragma unroll
        for (int l = 0; l < 32; l++) s += sctx[l] * U[l * uLen + j];
        su[j] = s;
    }
    for (int j = tid; j < vLen; j += blockDim.x) {
        float s = 0.f;
        #pragma unroll
        for (int l = 0; l < 32; l++) s += sctx[l] * V[l * vLen + j];
        sv[j] = s;
    }
    __syncthreads();

    for (int widx = tid; widx < wN; widx += blockDim.x) {
        int o = widx / IKK, k = widx - o * IKK;
        float m = 0.f;
        #pragma unroll
        for (int r = 0; r < 16; r++) m += su[r * O + o] * sv[r * IKK + k];
        gw[widx] = W[widx] * (1.0f + m + 1e-3f);
    }
    if (tid < O) {
        float s = 0.f;
        #pragma unroll
        for (int l = 0; l < 32; l++) s += sctx[l] * Bb[l * O + tid];
        gb[tid] = s;
    }
}

// ---------------- role bodies ----------------

// conv 3x3 s1 p1; tile TWxTH, all 8 out channels
template<int H, int TW, int TH>
__device__ __forceinline__ void conv3_body(float* sm, const float* xb, int b,
                                           int x0, int y0, int tid, int stage) {
    constexpr int IW = TW + 2, IH = TH + 2;
    float* sIn = sm;
    float* sW  = sm + CH * IH * IW;
    float* sB  = sW + CH * CH * 9;
    const float* wsrc = g_wr + (size_t)(stage * BATCH + b) * CH * CH * 9;
    for (int j = tid; j < CH * CH * 9; j += 256) sW[j] = wsrc[j];
    if (tid < CH) sB[tid] = g_br[(stage * BATCH + b) * CH + tid];
    for (int j = tid; j < CH * IH * IW; j += 256) {
        int i = j / (IH * IW);
        int rem = j - i * IH * IW;
        int r = rem / IW, c = rem - r * IW;
        int gy = y0 - 1 + r, gx = x0 - 1 + c;
        float v = 0.f;
        if ((unsigned)gy < (unsigned)H && (unsigned)gx < (unsigned)H)
            v = xb[i * H * H + gy * H + gx];
        sIn[j] = v;
    }
    __syncthreads();
    if (tid < TW * CH) {
        int tx = tid & (TW - 1);
        int o  = tid / TW;
        float acc[TH];
        float bias = sB[o];
        #pragma unroll
        for (int y = 0; y < TH; y++) acc[y] = bias;
        #pragma unroll
        for (int i = 0; i < CH; i++) {
            float w[9];
            #pragma unroll
            for (int k = 0; k < 9; k++) w[k] = sW[(o * CH + i) * 9 + k];
            #pragma unroll
            for (int r = 0; r < IH; r++) {
                float v[3];
                #pragma unroll
                for (int k = 0; k < 3; k++) v[k] = sIn[(i * IH + r) * IW + tx + k];
                #pragma unroll
                for (int ky = 0; ky < 3; ky++) {
                    int y = r - ky;
                    if (y >= 0 && y < TH) {
                        #pragma unroll
                        for (int kx = 0; kx < 3; kx++)
                            acc[y] += v[kx] * w[ky * 3 + kx];
                    }
                }
            }
        }
        int bo = b * CH + o;
        float* outp = g_pos + (size_t)bo * H * H;
        float mn = 3.4e38f;
        #pragma unroll
        for (int y = 0; y < TH; y++) {
            outp[(y0 + y) * H + x0 + tx] = acc[y];
            mn = fminf(mn, fabsf(acc[y]));
        }
        #pragma unroll
        for (int off = TW / 2; off > 0; off >>= 1)
            mn = fminf(mn, __shfl_down_sync(0xFFFFFFFFu, mn, off, TW));
        if (tx == 0) atomicMin(&g_minpos[stage * BATCH * CH + bo], __float_as_uint(mn));
    }
}

// convT 4x4 s2 p1 on -x, parity-decomposed; output tile 32x8 at OH
template<int H>
__device__ __forceinline__ void convt_body(float* sm, const float* x, int b,
                                           int x0, int y0, int tid, int stage) {
    constexpr int OH = 2 * H;
    constexpr int TW = 32, TH = 8;
    constexpr int IWT = TW / 2 + 2;   // 18
    constexpr int IHT = TH / 2 + 2;   // 6
    float* sIn = sm;                          // CH*IHT*IWT
    float* sW  = sm + CH * IHT * IWT;
    float* sB  = sW + CH * CH * 16;
    const float* wsrc = g_wt + (size_t)(stage * BATCH + b) * CH * CH * 16;
    if (tid < CH) sB[tid] = g_bt[(stage * BATCH + b) * CH + tid];
    for (int j = tid; j < CH * CH * 16; j += 256) sW[j] = wsrc[j];
    int ix0 = x0 / 2 - 1, iy0 = y0 / 2 - 1;
    for (int j = tid; j < CH * IHT * IWT; j += 256) {
        int i = j / (IHT * IWT);
        int rem = j - i * IHT * IWT;
        int r = rem / IWT, c = rem - r * IWT;
        int gy = iy0 + r, gx = ix0 + c;
        float v = 0.f;
        if ((unsigned)gy < (unsigned)H && (unsigned)gx < (unsigned)H)
            v = x[i * H * H + gy * H + gx];
        sIn[j] = v;
    }
    __syncthreads();

    int tx = tid & 31, o = tid >> 5;
    int px = tx & 1;
    int cA = (tx >> 1) + px;
    float acc[TH];
    float bias = sB[o];
    #pragma unroll
    for (int y = 0; y < TH; y++) acc[y] = bias;

    #pragma unroll
    for (int i = 0; i < CH; i++) {
        float wA[4], wB[4];
        #pragma unroll
        for (int ky = 0; ky < 4; ky++) {
            wA[ky] = sW[(o * CH + i) * 16 + ky * 4 + (3 - px)];
            wB[ky] = sW[(o * CH + i) * 16 + ky * 4 + (1 - px)];
        }
        float vA[IHT], vB[IHT];
        #pragma unroll
        for (int r = 0; r < IHT; r++) {
            vA[r] = sIn[(i * IHT + r) * IWT + cA];
            vB[r] = sIn[(i * IHT + r) * IWT + cA + 1];
        }
        #pragma unroll
        for (int ty = 0; ty < TH; ty++) {
            const int py = ty & 1;
            const int r = (ty >> 1) + py;
            acc[ty] -= vA[r]     * wA[3 - py]
                     + vB[r]     * wB[3 - py]
                     + vA[r + 1] * wA[1 - py]
                     + vB[r + 1] * wB[1 - py];
        }
    }

    int bo = b * CH + o;
    float* outp = g_neg + (size_t)bo * OH * OH;
    float mn = 3.4e38f;
    #pragma unroll
    for (int y = 0; y < TH; y++) {
        outp[(y0 + y) * OH + x0 + tx] = acc[y];
        mn = fminf(mn, fabsf(acc[y]));
    }
    #pragma unroll
    for (int off = 16; off > 0; off >>= 1)
        mn = fminf(mn, __shfl_down_sync(0xFFFFFFFFu, mn, off));
    if (tx == 0) atomicMin(&g_minneg[stage * BATCH * CH + bo], __float_as_uint(mn));
}

// conv 5x5 s1 p2 on bilinear-upsampled log(|x|+1), fused loader; tile 32x8 at OH
template<int H>
__device__ __forceinline__ void conv5_body(float* sm, const float* xb, int b,
                                           int x0, int y0, int tid, int stage) {
    constexpr int OH = 2 * H;
    constexpr int LH = 8, LW = 20;     // lx tile (H-res)
    constexpr int IH = 12, IW = 36;    // xu tile (OH-res)
    float* sLx = sm;                           // 1280
    float* sXu = sm + CH * LH * LW;            // 3456
    float* sW  = sXu + CH * IH * IW;           // 1600
    float* sB  = sW + CH * CH * 25;
    const float* wsrc = g_wm + (size_t)(stage * BATCH + b) * CH * CH * 25;
    for (int j = tid; j < CH * CH * 25; j += 256) sW[j] = wsrc[j];
    if (tid < CH) sB[tid] = g_bm[(stage * BATCH + b) * CH + tid];

    int gyLo = ((y0 - 2) >> 1) - 1;
    int gxLo = ((x0 - 2) >> 1) - 1;
    for (int j = tid; j < CH * LH * LW; j += 256) {
        int i = j / (LH * LW);
        int rem = j - i * LH * LW;
        int r = rem / LW, c = rem - r * LW;
        int gy = gyLo + r, gx = gxLo + c;
        float v = 0.f;
        if ((unsigned)gy < (unsigned)H && (unsigned)gx < (unsigned)H)
            v = logf(fabsf(xb[i * H * H + gy * H + gx]) + 1.0f);
        sLx[j] = v;
    }
    __syncthreads();
    for (int j = tid; j < CH * IH * IW; j += 256) {
        int i = j / (IH * IW);
        int rem = j - i * IH * IW;
        int r = rem / IW, c = rem - r * IW;
        int Y = y0 - 2 + r, X = x0 - 2 + c;
        float v = 0.f;
        if ((unsigned)Y < (unsigned)OH && (unsigned)X < (unsigned)OH) {
            int iy = Y >> 1, ix = X >> 1;
            int yo = (Y & 1) ? min(iy + 1, H - 1) : max(iy - 1, 0);
            int xo = (X & 1) ? min(ix + 1, H - 1) : max(ix - 1, 0);
            const float* L = sLx + i * LH * LW;
            int ry = iy - gyLo, ryo = yo - gyLo;
            int cx = ix - gxLo, cxo = xo - gxLo;
            v = 0.5625f * L[ry * LW + cx] + 0.1875f * L[ry * LW + cxo]
              + 0.1875f * L[ryo * LW + cx] + 0.0625f * L[ryo * LW + cxo];
        }
        sXu[j] = v;
    }
    __syncthreads();

    int tx = tid & 31, o = tid >> 5;
    float acc[8];
    float bias = sB[o];
    #pragma unroll
    for (int y = 0; y < 8; y++) acc[y] = bias;
    #pragma unroll
    for (int i = 0; i < CH; i++) {
        float w[25];
        #pragma unroll
        for (int k = 0; k < 25; k++) w[k] = sW[(o * CH + i) * 25 + k];
        #pragma unroll
        for (int r = 0; r < IH; r++) {
            float v[5];
            #pragma unroll
            for (int k = 0; k < 5; k++) v[k] = sXu[(i * IH + r) * IW + tx + k];
            #pragma unroll
            for (int ky = 0; ky < 5; ky++) {
                int y = r - ky;
                if (y >= 0 && y < 8) {
                    #pragma unroll
                    for (int kx = 0; kx < 5; kx++)
                        acc[y] += v[kx] * w[ky * 5 + kx];
                }
            }
        }
    }
    int bo = b * CH + o;
    float* outp = g_mul + (size_t)bo * OH * OH;
    float mn = 3.4e38f;
    #pragma unroll
    for (int y = 0; y < 8; y++) {
        outp[(y0 + y) * OH + x0 + tx] = acc[y];
        mn = fminf(mn, fabsf(acc[y]));
    }
    #pragma unroll
    for (int off = 16; off > 0; off >>= 1)
        mn = fminf(mn, __shfl_down_sync(0xFFFFFFFFu, mn, off));
    if (tx == 0) atomicMin(&g_minmul[stage * BATCH * CH + bo], __float_as_uint(mn));
}

// ---------------- per-stage superkernel ----------------
// grid: (OH/32, OH/8, 192); z = role*64 + b
template<int STAGE>
__global__ __launch_bounds__(256) void k_stage(int srcA) {
    constexpr int H = 16 << STAGE;
    __shared__ float smem[6400];
    int role = blockIdx.z >> 6;
    int b = blockIdx.z & 63;
    int tid = threadIdx.x;
    const float* xb = (srcA ? g_xA : g_xB) + (size_t)b * CH * H * H;

    if (role == 0) {
        constexpr int TW = (STAGE == 0) ? 16 : 32;
        if ((int)blockIdx.x >= H / TW || (int)blockIdx.y >= H / 8) return;
        conv3_body<H, TW, 8>(smem, xb, b, blockIdx.x * TW, blockIdx.y * 8, tid, STAGE);
    } else if (role == 1) {
        convt_body<H>(smem, xb, b, blockIdx.x * 32, blockIdx.y * 8, tid, STAGE);
    } else {
        conv5_body<H>(smem, xb, b, blockIdx.x * 32, blockIdx.y * 8, tid, STAGE);
    }
}

// ---------------- combine (stages 0-2): writes next x ----------------
template<int H>
__global__ __launch_bounds__(256) void k_combine(int stage, int dstA) {
    constexpr int OH = 2 * H;
    constexpr int NH = H * H;
    int t = blockIdx.x * 256 + threadIdx.x;
    if (t >= BATCH * CH * NH) return;
    int bc = t / NH;
    int rem = t - bc * NH;
    int y = rem / H, x = rem - y * H;
    float mnp = __uint_as_float(g_minpos[stage * BATCH * CH + bc]);
    float mnn = __uint_as_float(g_minneg[stage * BATCH * CH + bc]);
    float mnm = __uint_as_float(g_minmul[stage * BATCH * CH + bc]);
    float dp = dln_f(g_pos[(size_t)bc * NH + rem], mnp);
    const float2* neg2 = (const float2*)(g_neg + (size_t)bc * OH * OH);
    const float2* mul2 = (const float2*)(g_mul + (size_t)bc * OH * OH);
    float2* dst2 = (float2*)((dstA ? g_xA : g_xB) + (size_t)bc * OH * OH);
    #pragma unroll
    for (int dy = 0; dy < 2; dy++) {
        int row = 2 * y + dy;
        float2 n = neg2[row * (OH / 2) + x];
        float2 m = mul2[row * (OH / 2) + x];
        float2 r;
        r.x = (dp + dln_f(n.x, mnn)) * dln_f(m.x, mnm);
        r.y = (dp + dln_f(n.y, mnn)) * dln_f(m.y, mnm);
        dst2[row * (OH / 2) + x] = r;
    }
}

// ---------------- stage-3 combine fused with final 1x1 conv -> 3 ch ----------------
__global__ __launch_bounds__(256) void k_comfinal(float* __restrict__ out) {
    constexpr int H = 128, OH = 256, NH = H * H;
    constexpr int stage = 3;
    int t = blockIdx.x * 256 + threadIdx.x;   // t < 64*NH
    int b = t / NH;
    int rem = t - b * NH;
    int y = rem / H, x = rem - y * H;

    float wo[3 * CH], bo3[3];
    #pragma unroll
    for (int k = 0; k < 3 * CH; k++) wo[k] = g_wo[b * 3 * CH + k];
    #pragma unroll
    for (int k = 0; k < 3; k++) bo3[k] = g_bo[b * 3 + k];

    float dp[CH], mnn[CH], mnm[CH];
    #pragma unroll
    for (int c = 0; c < CH; c++) {
        int bc = b * CH + c;
        float mnp = __uint_as_float(g_minpos[stage * BATCH * CH + bc]);
        mnn[c] = __uint_as_float(g_minneg[stage * BATCH * CH + bc]);
        mnm[c] = __uint_as_float(g_minmul[stage * BATCH * CH + bc]);
        dp[c] = dln_f(g_pos[(size_t)bc * NH + rem], mnp);
    }

    #pragma unroll
    for (int dy = 0; dy < 2; dy++) {
        int row = 2 * y + dy;
        float2 acc[3];
        #pragma unroll
        for (int o = 0; o < 3; o++) { acc[o].x = bo3[o]; acc[o].y = bo3[o]; }
        #pragma unroll
        for (int c = 0; c < CH; c++) {
            int bc = b * CH + c;
            const float2* neg2 = (const float2*)(g_neg + (size_t)bc * OH * OH);
            const float2* mul2 = (const float2*)(g_mul + (size_t)bc * OH * OH);
            float2 n = neg2[row * (OH / 2) + x];
            float2 m = mul2[row * (OH / 2) + x];
            float xv0 = (dp[c] + dln_f(n.x, mnn[c])) * dln_f(m.x, mnm[c]);
            float xv1 = (dp[c] + dln_f(n.y, mnn[c])) * dln_f(m.y, mnm[c]);
            #pragma unroll
            for (int o = 0; o < 3; o++) {
                acc[o].x += wo[o * CH + c] * xv0;
                acc[o].y += wo[o * CH + c] * xv1;
            }
        }
        #pragma unroll
        for (int o = 0; o < 3; o++) {
            float2* dst2 = (float2*)(out + ((size_t)b * 3 + o) * OH * OH);
            dst2[row * (OH / 2) + x] = acc[o];
        }
    }
}

// ---------------- launcher ----------------
extern "C" void kernel_launch(void* const* d_in, const int* in_sizes, int n_in,
                              void* d_out, int out_size) {
    const int*   ids = (const int*)  d_in[0];
    const float* cc  = (const float*)d_in[1];
    const float* lat = (const float*)d_in[2];
    const float* Wr = (const float*)d_in[3];
    const float* Ur = (const float*)d_in[4];
    const float* Vr = (const float*)d_in[5];
    const float* Br = (const float*)d_in[6];
    const float* Wt = (const float*)d_in[7];
    const float* Ut = (const float*)d_in[8];
    const float* Vt = (const float*)d_in[9];
    const float* Bt = (const float*)d_in[10];
    const float* Wm = (const float*)d_in[11];
    const float* Um = (const float*)d_in[12];
    const float* Vm = (const float*)d_in[13];
    const float* Bm = (const float*)d_in[14];
    const float* Wo = (const float*)d_in[15];
    const float* Uo = (const float*)d_in[16];
    const float* Vo = (const float*)d_in[17];
    const float* Bo = (const float*)d_in[18];

    k_gather<<<64, 256>>>(ids, cc, lat);
    k_weights<<<dim3(13, 64), 128>>>(Wr, Ur, Vr, Br, Wt, Ut, Vt, Bt,
                                     Wm, Um, Vm, Bm, Wo, Uo, Vo, Bo);
    k_mininit<<<(NSTAGE * BATCH * CH + 255) / 256, 256>>>();

    // stage 0: H=16, OH=32
    k_stage<0><<<dim3(1, 4, 192), 256>>>(1);
    k_combine<16><<<(BATCH * CH * 16 * 16 + 255) / 256, 256>>>(0, 0);
    // stage 1: H=32, OH=64
    k_stage<1><<<dim3(2, 8, 192), 256>>>(0);
    k_combine<32><<<(BATCH * CH * 32 * 32 + 255) / 256, 256>>>(1, 1);
    // stage 2: H=64, OH=128
    k_stage<2><<<dim3(4, 16, 192), 256>>>(1);
    k_combine<64><<<(BATCH * CH * 64 * 64 + 255) / 256, 256>>>(2, 0);
    // stage 3: H=128, OH=256 (combine fused with final 1x1)
    k_stage<3><<<dim3(8, 32, 192), 256>>>(0);
    k_comfinal<<<(BATCH * 128 * 128 + 255) / 256, 256>>>((float*)d_out);
}